// round 2
// baseline (speedup 1.0000x reference)
#include <cuda_runtime.h>
#include <math.h>
#include <stddef.h>

#define NNODES 16383
#define DSSM   512
#define DSTATE 16
#define KIN    513
#define NINT   8191          // internal nodes (store H only for these)
#define NCOL2  544           // 512 delta + 16 B + 16 C

// ------------------------- scratch (device globals; no mallocs allowed) ----
__device__ float g_x[(size_t)NNODES * DSSM];
__device__ float g_delta[(size_t)NNODES * DSSM];
__device__ float g_Bv[(size_t)NNODES * DSTATE];
__device__ float g_Cv[(size_t)NNODES * DSTATE];
__device__ float g_logw[NNODES];
__device__ float g_negAT[DSTATE * DSSM];                 // [s][d] = -exp(A_log[d][s])
__device__ float g_H[(size_t)NINT * DSSM * DSTATE];      // [node][s][d], internal only

// ------------------------- prep: logw and -exp(A_log) ----------------------
__global__ void prep_kernel(const float* __restrict__ w, const float* __restrict__ Alog) {
    int i = blockIdx.x * blockDim.x + threadIdx.x;
    if (i < NNODES) g_logw[i] = logf(w[i] + 1e-6f);
    if (i < DSTATE * DSSM) {
        int s = i >> 9, d = i & 511;
        g_negAT[i] = -expf(Alog[d * DSTATE + s]);
    }
}

// ------------------------- GEMM1: x = [s | logw] @ W_in^T + b_in -----------
// M=16383, K=513, N=512.  128x128x16 tiles, 256 threads, 8x8 per thread.
__global__ __launch_bounds__(256) void gemm1_kernel(
    const float* __restrict__ S, const float* __restrict__ Win,
    const float* __restrict__ bin)
{
    __shared__ float As[16][132];
    __shared__ float Bs[16][132];
    int tid = threadIdx.x;
    int tx = tid & 15, ty = tid >> 4;
    int rowBase = blockIdx.y * 128;
    int colBase = blockIdx.x * 128;
    int lr = tid >> 1;           // 0..127
    int lc = (tid & 1) * 8;      // 0 or 8

    float acc[8][8];
#pragma unroll
    for (int i = 0; i < 8; i++)
#pragma unroll
        for (int j = 0; j < 8; j++) acc[i][j] = 0.f;

    for (int kt = 0; kt < 33; kt++) {
        int k0 = kt * 16;
        // --- A tile (feat) ---
        int gr = rowBase + lr;
        if (kt < 32) {
            float4 v0 = {0, 0, 0, 0}, v1 = {0, 0, 0, 0};
            if (gr < NNODES) {
                const float4* p = reinterpret_cast<const float4*>(S + (size_t)gr * 512 + k0 + lc);
                v0 = p[0]; v1 = p[1];
            }
            As[lc + 0][lr] = v0.x; As[lc + 1][lr] = v0.y; As[lc + 2][lr] = v0.z; As[lc + 3][lr] = v0.w;
            As[lc + 4][lr] = v1.x; As[lc + 5][lr] = v1.y; As[lc + 6][lr] = v1.z; As[lc + 7][lr] = v1.w;
        } else {
#pragma unroll
            for (int j = 0; j < 8; j++) {
                int gc = k0 + lc + j;
                float v = 0.f;
                if (gr < NNODES && gc == 512) v = g_logw[gr];
                As[lc + j][lr] = v;
            }
        }
        // --- B tile (W_in rows, stride 513 -> scalar loads) ---
        int gd = colBase + lr;   // always < 512
#pragma unroll
        for (int j = 0; j < 8; j++) {
            int gc = k0 + lc + j;
            float v = (gc < KIN) ? Win[(size_t)gd * KIN + gc] : 0.f;
            Bs[lc + j][lr] = v;
        }
        __syncthreads();
#pragma unroll
        for (int kk = 0; kk < 16; kk++) {
            float a[8], b[8];
            const float4* pa = reinterpret_cast<const float4*>(&As[kk][ty * 8]);
            const float4* pb = reinterpret_cast<const float4*>(&Bs[kk][tx * 8]);
            *reinterpret_cast<float4*>(&a[0]) = pa[0];
            *reinterpret_cast<float4*>(&a[4]) = pa[1];
            *reinterpret_cast<float4*>(&b[0]) = pb[0];
            *reinterpret_cast<float4*>(&b[4]) = pb[1];
#pragma unroll
            for (int i = 0; i < 8; i++)
#pragma unroll
                for (int j = 0; j < 8; j++) acc[i][j] = fmaf(a[i], b[j], acc[i][j]);
        }
        __syncthreads();
    }
#pragma unroll
    for (int i = 0; i < 8; i++) {
        int gr = rowBase + ty * 8 + i;
        if (gr >= NNODES) continue;
#pragma unroll
        for (int j = 0; j < 8; j++) {
            int gc = colBase + tx * 8 + j;
            g_x[(size_t)gr * 512 + gc] = acc[i][j] + bin[gc];
        }
    }
}

// --------- GEMM2: z = x @ [W_delta; W_B; W_C]^T, fused epilogues -----------
// M=16383, K=512, N=544 (cols 0..511 delta-transform, 512..527 B, 528..543 C)
__global__ __launch_bounds__(256) void gemm2_kernel(
    const float* __restrict__ Wd, const float* __restrict__ bd,
    const float* __restrict__ Ww, const float* __restrict__ bw,
    const float* __restrict__ WB, const float* __restrict__ bB,
    const float* __restrict__ WC, const float* __restrict__ bC)
{
    __shared__ float As[16][132];
    __shared__ float Bs[16][132];
    int tid = threadIdx.x;
    int tx = tid & 15, ty = tid >> 4;
    int rowBase = blockIdx.y * 128;
    int colBase = blockIdx.x * 128;
    int lr = tid >> 1;
    int lc = (tid & 1) * 8;

    // row pointer for this thread's B-tile row
    int gj = colBase + lr;
    const float* rp = nullptr;
    if (gj < 512)        rp = Wd + (size_t)gj * 512;
    else if (gj < 528)   rp = WB + (size_t)(gj - 512) * 512;
    else if (gj < NCOL2) rp = WC + (size_t)(gj - 528) * 512;

    float acc[8][8];
#pragma unroll
    for (int i = 0; i < 8; i++)
#pragma unroll
        for (int j = 0; j < 8; j++) acc[i][j] = 0.f;

    for (int kt = 0; kt < 32; kt++) {
        int k0 = kt * 16;
        int gr = rowBase + lr;
        float4 a0 = {0, 0, 0, 0}, a1 = {0, 0, 0, 0};
        if (gr < NNODES) {
            const float4* p = reinterpret_cast<const float4*>(g_x + (size_t)gr * 512 + k0 + lc);
            a0 = p[0]; a1 = p[1];
        }
        As[lc + 0][lr] = a0.x; As[lc + 1][lr] = a0.y; As[lc + 2][lr] = a0.z; As[lc + 3][lr] = a0.w;
        As[lc + 4][lr] = a1.x; As[lc + 5][lr] = a1.y; As[lc + 6][lr] = a1.z; As[lc + 7][lr] = a1.w;

        float4 b0 = {0, 0, 0, 0}, b1 = {0, 0, 0, 0};
        if (rp) {
            const float4* p = reinterpret_cast<const float4*>(rp + k0 + lc);
            b0 = p[0]; b1 = p[1];
        }
        Bs[lc + 0][lr] = b0.x; Bs[lc + 1][lr] = b0.y; Bs[lc + 2][lr] = b0.z; Bs[lc + 3][lr] = b0.w;
        Bs[lc + 4][lr] = b1.x; Bs[lc + 5][lr] = b1.y; Bs[lc + 6][lr] = b1.z; Bs[lc + 7][lr] = b1.w;

        __syncthreads();
#pragma unroll
        for (int kk = 0; kk < 16; kk++) {
            float a[8], b[8];
            const float4* pa = reinterpret_cast<const float4*>(&As[kk][ty * 8]);
            const float4* pb = reinterpret_cast<const float4*>(&Bs[kk][tx * 8]);
            *reinterpret_cast<float4*>(&a[0]) = pa[0];
            *reinterpret_cast<float4*>(&a[4]) = pa[1];
            *reinterpret_cast<float4*>(&b[0]) = pb[0];
            *reinterpret_cast<float4*>(&b[4]) = pb[1];
#pragma unroll
            for (int i = 0; i < 8; i++)
#pragma unroll
                for (int j = 0; j < 8; j++) acc[i][j] = fmaf(a[i], b[j], acc[i][j]);
        }
        __syncthreads();
    }
#pragma unroll
    for (int i = 0; i < 8; i++) {
        int gr = rowBase + ty * 8 + i;
        if (gr >= NNODES) continue;
        float lw = g_logw[gr];
#pragma unroll
        for (int j = 0; j < 8; j++) {
            int gc = colBase + tx * 8 + j;
            if (gc >= NCOL2) continue;
            float z = acc[i][j];
            if (gc < 512) {
                z += bd[gc];
                float sp = (z > 20.f) ? z : log1pf(expf(z));
                float t = lw * Ww[gc] + bw[gc];
                float sg = 1.f / (1.f + expf(-t));
                g_delta[(size_t)gr * 512 + gc] = sp * sg;
            } else if (gc < 528) {
                g_Bv[(size_t)gr * 16 + (gc - 512)] = z + bB[gc - 512];
            } else {
                g_Cv[(size_t)gr * 16 + (gc - 528)] = z + bC[gc - 528];
            }
        }
    }
}

// ---------- walker: levels 0..6 (nodes 0..126), one thread per (d,s) -------
__global__ __launch_bounds__(512) void walker_kernel() {
    int g = blockIdx.x * blockDim.x + threadIdx.x;   // 8192 threads
    int d = g & 511;
    int s2 = g >> 9;
    float An = g_negAT[s2 * 512 + d];
    float hl[127];
#pragma unroll 1
    for (int n = 0; n < 127; n++) {
        float dn = g_delta[(size_t)n * 512 + d];
        float xn = g_x[(size_t)n * 512 + d];
        float a = __expf(dn * An);
        float b = dn * xn * g_Bv[(size_t)n * 16 + s2];
        float hp = (n == 0) ? 0.f : hl[(n - 1) >> 1];
        float h = fmaf(a, hp, b);
        hl[n] = h;
        g_H[(size_t)n * 8192 + s2 * 512 + d] = h;
    }
}

// ---------------------- fused LayerNorm write ------------------------------
__device__ __forceinline__ void ln_write(float y, int n, int d,
                                         const float* __restrict__ gamma,
                                         const float* __restrict__ beta,
                                         float* __restrict__ out)
{
    __shared__ float rs[16], rs2[16];
    float v = y, v2 = y * y;
#pragma unroll
    for (int o = 16; o; o >>= 1) {
        v  += __shfl_down_sync(0xffffffffu, v,  o);
        v2 += __shfl_down_sync(0xffffffffu, v2, o);
    }
    int wp = d >> 5, lane = d & 31;
    if (lane == 0) { rs[wp] = v; rs2[wp] = v2; }
    __syncthreads();
    if (wp == 0) {
        float a = (lane < 16) ? rs[lane]  : 0.f;
        float b = (lane < 16) ? rs2[lane] : 0.f;
#pragma unroll
        for (int o = 8; o; o >>= 1) {
            a += __shfl_down_sync(0xffffffffu, a, o);
            b += __shfl_down_sync(0xffffffffu, b, o);
        }
        if (lane == 0) { rs[0] = a * (1.f / 512.f); rs2[0] = b * (1.f / 512.f); }
    }
    __syncthreads();
    float mu = rs[0];
    float var = rs2[0] - mu * mu;
    out[(size_t)n * 512 + d] = (y - mu) * rsqrtf(var + 1e-5f) * gamma[d] + beta[d];
}

// ---------- readout for nodes 0..126 (H already in global) -----------------
__global__ __launch_bounds__(512) void readout0_kernel(
    const float* __restrict__ Dv, const float* __restrict__ gamma,
    const float* __restrict__ beta, float* __restrict__ out)
{
    int n = blockIdx.x;
    int d = threadIdx.x;
    float y = Dv[d] * g_x[(size_t)n * 512 + d];
#pragma unroll
    for (int s = 0; s < 16; s++)
        y = fmaf(g_H[(size_t)n * 8192 + s * 512 + d], g_Cv[(size_t)n * 16 + s], y);
    ln_write(y, n, d, gamma, beta, out);
}

// ---------- per-level scan + fused readout + LN ----------------------------
template <bool WRITE_H>
__global__ __launch_bounds__(512) void level_kernel(
    int off, const float* __restrict__ Dv, const float* __restrict__ gamma,
    const float* __restrict__ beta, float* __restrict__ out)
{
    int n = off + blockIdx.x;
    int d = threadIdx.x;
    int par = (n - 1) >> 1;
    float dn = g_delta[(size_t)n * 512 + d];
    float xn = g_x[(size_t)n * 512 + d];
    float dx = dn * xn;
    float y = Dv[d] * xn;
    const float* Hp = g_H + (size_t)par * 8192 + d;
    float* Hn = g_H + (size_t)n * 8192 + d;
#pragma unroll
    for (int s = 0; s < 16; s++) {
        float a = __expf(dn * g_negAT[s * 512 + d]);
        float h = fmaf(a, Hp[(size_t)s * 512], dx * g_Bv[(size_t)n * 16 + s]);
        if (WRITE_H) Hn[(size_t)s * 512] = h;
        y = fmaf(h, g_Cv[(size_t)n * 16 + s], y);
    }
    ln_write(y, n, d, gamma, beta, out);
}

// ---------------------------------------------------------------------------
extern "C" void kernel_launch(void* const* d_in, const int* in_sizes, int n_in,
                              void* d_out, int out_size)
{
    const float* s    = (const float*)d_in[0];
    const float* w    = (const float*)d_in[1];
    // d_in[2]=parent, d_in[3]=depth: structural for the complete binary tree; unused
    const float* Win  = (const float*)d_in[4];
    const float* bin  = (const float*)d_in[5];
    const float* Wd   = (const float*)d_in[6];
    const float* bd   = (const float*)d_in[7];
    const float* Ww   = (const float*)d_in[8];
    const float* bw   = (const float*)d_in[9];
    const float* Alog = (const float*)d_in[10];
    const float* Dv   = (const float*)d_in[11];
    const float* WB   = (const float*)d_in[12];
    const float* bB   = (const float*)d_in[13];
    const float* WC   = (const float*)d_in[14];
    const float* bC   = (const float*)d_in[15];
    const float* gam  = (const float*)d_in[16];
    const float* bet  = (const float*)d_in[17];
    float* out = (float*)d_out;

    prep_kernel<<<64, 256>>>(w, Alog);
    gemm1_kernel<<<dim3(4, 128), 256>>>(s, Win, bin);
    gemm2_kernel<<<dim3(5, 128), 256>>>(Wd, bd, Ww, bw, WB, bB, WC, bC);
    walker_kernel<<<16, 512>>>();
    readout0_kernel<<<127, 512>>>(Dv, gam, bet, out);
    for (int l = 7; l < 13; l++)
        level_kernel<true><<<1 << l, 512>>>((1 << l) - 1, Dv, gam, bet, out);
    level_kernel<false><<<8192, 512>>>(8191, Dv, gam, bet, out);
}

// round 4
// speedup vs baseline: 1.5795x; 1.5795x over previous
#include <cuda_runtime.h>
#include <cuda_bf16.h>
#include <math.h>
#include <stddef.h>
#include <stdint.h>

#define NNODES 16383
#define NHMAX  2047          // H stored only for nodes < 2047 (levels <= 10)

// ------------------------- device scratch ----------------------------------
__device__ __align__(256) float g_x[(size_t)NNODES * 512];
__device__ __align__(256) float g_delta[(size_t)NNODES * 512];
__device__ __align__(256) float g_Bv[(size_t)NNODES * 16];
__device__ __align__(256) float g_Cv[(size_t)NNODES * 16];
__device__ __align__(256) float g_logw[NNODES];
__device__ __align__(256) float g_negAT[16 * 512];               // [s][d] = -exp(A_log[d][s])
__device__ __align__(256) float g_H[(size_t)NHMAX * 8192];       // [node][s][d]
__device__ __align__(256) __nv_bfloat16 g_S_hl[(size_t)NNODES * 1024];  // [row][hi512|lo512]
__device__ __align__(256) __nv_bfloat16 g_x_hl[(size_t)NNODES * 1024];
__device__ __align__(256) __nv_bfloat16 g_Wi_hl[512 * 1024];
__device__ __align__(256) __nv_bfloat16 g_Wd_hl[512 * 1024];
__device__ __align__(256) __nv_bfloat16 g_BC_hl[32 * 1024];      // rows 0..15 = W_B, 16..31 = W_C

// ------------------------- small helpers -----------------------------------
__device__ __forceinline__ uint32_t smem_u32(const void* p) {
    uint32_t a;
    asm("{ .reg .u64 t; cvta.to.shared.u64 t, %1; cvt.u32.u64 %0, t; }" : "=r"(a) : "l"(p));
    return a;
}
__device__ __forceinline__ void cp16(uint32_t dst, const void* src, int sz) {
    asm volatile("cp.async.cg.shared.global [%0], [%1], 16, %2;"
                 :: "r"(dst), "l"(src), "r"(sz) : "memory");
}
__device__ __forceinline__ uint32_t lds32(uint32_t a) {
    uint32_t v;
    asm volatile("ld.shared.b32 %0, [%1];" : "=r"(v) : "r"(a));
    return v;
}
__device__ __forceinline__ void mma16816(float* c, const uint32_t* a, const uint32_t* b) {
    asm volatile(
        "mma.sync.aligned.m16n8k16.row.col.f32.bf16.bf16.f32 "
        "{%0,%1,%2,%3}, {%4,%5,%6,%7}, {%8,%9}, {%0,%1,%2,%3};"
        : "+f"(c[0]), "+f"(c[1]), "+f"(c[2]), "+f"(c[3])
        : "r"(a[0]), "r"(a[1]), "r"(a[2]), "r"(a[3]), "r"(b[0]), "r"(b[1]));
}
__device__ __forceinline__ void split2(float v, __nv_bfloat16& h, __nv_bfloat16& l) {
    h = __float2bfloat16_rn(v);
    l = __float2bfloat16_rn(v - __bfloat162float(h));
}

// ------------------------- prep kernels ------------------------------------
__global__ void prepW_kernel(const float* __restrict__ w, const float* __restrict__ Alog,
                             const float* __restrict__ Win, const float* __restrict__ Wd,
                             const float* __restrict__ WB, const float* __restrict__ WC)
{
    int i = blockIdx.x * blockDim.x + threadIdx.x;   // 262144 threads
    if (i < 262144) {
        int d = i >> 9, k = i & 511;
        __nv_bfloat16 h, l;
        split2(Win[(size_t)d * 513 + k], h, l);
        g_Wi_hl[(size_t)d * 1024 + k] = h; g_Wi_hl[(size_t)d * 1024 + 512 + k] = l;
        split2(Wd[(size_t)d * 512 + k], h, l);
        g_Wd_hl[(size_t)d * 1024 + k] = h; g_Wd_hl[(size_t)d * 1024 + 512 + k] = l;
    }
    if (i < 16384) {
        int r = i >> 9, k = i & 511;
        float v = (r < 16) ? WB[(size_t)r * 512 + k] : WC[(size_t)(r - 16) * 512 + k];
        __nv_bfloat16 h, l; split2(v, h, l);
        g_BC_hl[(size_t)r * 1024 + k] = h; g_BC_hl[(size_t)r * 1024 + 512 + k] = l;
    }
    if (i < NNODES) g_logw[i] = logf(w[i] + 1e-6f);
    if (i < 8192) {
        int s = i >> 9, d = i & 511;
        g_negAT[i] = -expf(Alog[d * 16 + s]);
    }
}

__global__ void prepS_kernel(const float* __restrict__ s) {
    int idx = blockIdx.x * blockDim.x + threadIdx.x;
    if (idx >= NNODES * 128) return;
    int r = idx >> 7, c4 = idx & 127;
    float4 v = reinterpret_cast<const float4*>(s)[idx];
    __align__(8) __nv_bfloat16 h[4], l[4];
    split2(v.x, h[0], l[0]); split2(v.y, h[1], l[1]);
    split2(v.z, h[2], l[2]); split2(v.w, h[3], l[3]);
    *reinterpret_cast<uint2*>(&g_S_hl[(size_t)r * 1024 + c4 * 4])       = *reinterpret_cast<uint2*>(h);
    *reinterpret_cast<uint2*>(&g_S_hl[(size_t)r * 1024 + 512 + c4 * 4]) = *reinterpret_cast<uint2*>(l);
}

// ------------------------- mma.sync GEMM ------------------------------------
// D[M=16383, BN-cols per x-block] = A @ B^T, bf16 hi/lo split (3 products).
// smem stage layout (bytes): Ah[0,4096) Al[4096,8192) Bh[8192,8192+BSZ) Bl[+BSZ]
// A/B tiles stored [row][16 bf16] = 32B rows.
template <int BN, int EPI>
__global__ __launch_bounds__(256, 1) void gemm_mma(
    const float* __restrict__ p0, const float* __restrict__ p1, const float* __restrict__ p2)
{
    constexpr int MT  = (BN == 128) ? 4 : 1;   // 16-row subtiles per warp
    constexpr int NT  = 4;                      // 8-col subtiles per warp
    constexpr int BSZ = BN * 32;                // bytes per B variant tile
    constexpr int STAGE = 8192 + 2 * BSZ;
    extern __shared__ char smem[];
    uint32_t sb = smem_u32(smem);

    const __nv_bfloat16* __restrict__ Ag = (EPI == 0) ? g_S_hl : g_x_hl;
    const __nv_bfloat16* __restrict__ Bg = (EPI == 0) ? g_Wi_hl : (EPI == 1 ? g_Wd_hl : g_BC_hl);

    const int tid = threadIdx.x;
    const int wid = tid >> 5, lane = tid & 31;
    const int g = lane >> 2, tig = lane & 3;
    const int warp_m = (BN == 128) ? (wid & 1) : wid;
    const int warp_n = (BN == 128) ? (wid >> 1) : 0;
    const int rowBase = blockIdx.y * 128;
    const int colBase = blockIdx.x * BN;

    float acc[MT][NT][4];
#pragma unroll
    for (int i = 0; i < MT; i++)
#pragma unroll
        for (int j = 0; j < NT; j++)
#pragma unroll
            for (int q = 0; q < 4; q++) acc[i][j][q] = 0.f;

    auto load_stage = [&](int it, int stg) {
        int k0 = it * 16;
        uint32_t D = sb + stg * STAGE;
        // A: 512 x 16B chunks
#pragma unroll
        for (int i = 0; i < 2; i++) {
            int q = tid + i * 256;
            int v = q >> 8;
            int rh = q & 255, r = rh >> 1, half = rh & 1;
            int gr = rowBase + r;
            int grc = gr < NNODES ? gr : 0;
            const char* src = (const char*)Ag + ((size_t)grc * 1024 + v * 512 + k0) * 2 + half * 16;
            cp16(D + v * 4096 + r * 32 + half * 16, src, gr < NNODES ? 16 : 0);
        }
        // B: BN*4 x 16B chunks
        constexpr int NB = BN * 4;
#pragma unroll
        for (int i = 0; i < (NB + 255) / 256; i++) {
            int q = tid + i * 256;
            if (NB >= 256 || q < NB) {
                int v = (q >= NB / 2) ? 1 : 0;
                int rh = q - v * (NB / 2), r = rh >> 1, half = rh & 1;
                const char* src = (const char*)Bg + ((size_t)(colBase + r) * 1024 + v * 512 + k0) * 2 + half * 16;
                cp16(D + 8192 + v * BSZ + r * 32 + half * 16, src, 16);
            }
        }
    };

    load_stage(0, 0);
    asm volatile("cp.async.commit_group;" ::: "memory");

    for (int it = 0; it < 32; it++) {
        if (it < 31) load_stage(it + 1, (it + 1) & 1);
        asm volatile("cp.async.commit_group;" ::: "memory");
        asm volatile("cp.async.wait_group 1;" ::: "memory");
        __syncthreads();

        uint32_t SB = sb + (it & 1) * STAGE;
        uint32_t ah[MT][4], al[MT][4], bh[NT][2], bl[NT][2];
#pragma unroll
        for (int mi = 0; mi < MT; mi++) {
            uint32_t base = SB + (warp_m * MT * 16 + mi * 16) * 32 + g * 32 + tig * 4;
            ah[mi][0] = lds32(base);        ah[mi][1] = lds32(base + 256);
            ah[mi][2] = lds32(base + 16);   ah[mi][3] = lds32(base + 256 + 16);
            base += 4096;
            al[mi][0] = lds32(base);        al[mi][1] = lds32(base + 256);
            al[mi][2] = lds32(base + 16);   al[mi][3] = lds32(base + 256 + 16);
        }
#pragma unroll
        for (int ni = 0; ni < NT; ni++) {
            uint32_t base = SB + 8192 + (warp_n * 32 + ni * 8) * 32 + g * 32 + tig * 4;
            bh[ni][0] = lds32(base);        bh[ni][1] = lds32(base + 16);
            base += BSZ;
            bl[ni][0] = lds32(base);        bl[ni][1] = lds32(base + 16);
        }
#pragma unroll
        for (int mi = 0; mi < MT; mi++)
#pragma unroll
            for (int ni = 0; ni < NT; ni++) {
                mma16816(acc[mi][ni], ah[mi], bh[ni]);
                mma16816(acc[mi][ni], ah[mi], bl[ni]);
                mma16816(acc[mi][ni], al[mi], bh[ni]);
            }
        __syncthreads();
    }

    // --------------------------- epilogue -----------------------------------
#pragma unroll
    for (int mi = 0; mi < MT; mi++) {
#pragma unroll
        for (int ni = 0; ni < NT; ni++) {
            int r0 = rowBase + warp_m * MT * 16 + mi * 16 + g;
            int c  = colBase + warp_n * 32 + ni * 8 + tig * 2;
#pragma unroll
            for (int h = 0; h < 2; h++) {
                int r = r0 + h * 8;
                if (r >= NNODES) continue;
                float v0 = acc[mi][ni][h * 2 + 0];
                float v1 = acc[mi][ni][h * 2 + 1];
                if (EPI == 0) {
                    float lw = g_logw[r];
                    float x0 = v0 + p0[c]     + lw * p1[(size_t)c * 513 + 512];
                    float x1 = v1 + p0[c + 1] + lw * p1[(size_t)(c + 1) * 513 + 512];
                    g_x[(size_t)r * 512 + c]     = x0;
                    g_x[(size_t)r * 512 + c + 1] = x1;
                    __nv_bfloat16 h0, l0, h1, l1;
                    split2(x0, h0, l0); split2(x1, h1, l1);
                    __nv_bfloat162 hp; hp.x = h0; hp.y = h1;
                    __nv_bfloat162 lp; lp.x = l0; lp.y = l1;
                    *reinterpret_cast<__nv_bfloat162*>(&g_x_hl[(size_t)r * 1024 + c])       = hp;
                    *reinterpret_cast<__nv_bfloat162*>(&g_x_hl[(size_t)r * 1024 + 512 + c]) = lp;
                } else if (EPI == 1) {
                    float lw = g_logw[r];
                    float z0 = v0 + p0[c], z1 = v1 + p0[c + 1];
                    float sp0 = (z0 > 20.f) ? z0 : log1pf(expf(z0));
                    float sp1 = (z1 > 20.f) ? z1 : log1pf(expf(z1));
                    float t0 = lw * p1[c] + p2[c];
                    float t1 = lw * p1[c + 1] + p2[c + 1];
                    g_delta[(size_t)r * 512 + c]     = sp0 / (1.f + expf(-t0));
                    g_delta[(size_t)r * 512 + c + 1] = sp1 / (1.f + expf(-t1));
                } else {
                    if (c < 16) {
                        g_Bv[(size_t)r * 16 + c]     = v0 + p0[c];
                        g_Bv[(size_t)r * 16 + c + 1] = v1 + p0[c + 1];
                    } else {
                        g_Cv[(size_t)r * 16 + (c - 16)]     = v0 + p1[c - 16];
                        g_Cv[(size_t)r * 16 + (c - 16) + 1] = v1 + p1[c - 15];
                    }
                }
            }
        }
    }
}

// ------------------------- scan building blocks ----------------------------
__device__ __forceinline__ void compute_h(int n, int d, const float* __restrict__ hp,
                                          float* __restrict__ h, float& dn_o, float& xn_o)
{
    float dn = g_delta[(size_t)n * 512 + d];
    float xn = g_x[(size_t)n * 512 + d];
    float dx = dn * xn;
#pragma unroll
    for (int s = 0; s < 16; s++) {
        float a = __expf(dn * g_negAT[s * 512 + d]);
        h[s] = fmaf(a, hp[s], dx * g_Bv[(size_t)n * 16 + s]);
    }
    dn_o = dn; xn_o = xn;
}
__device__ __forceinline__ void store_h(int n, int d, const float* __restrict__ h) {
#pragma unroll
    for (int s = 0; s < 16; s++) g_H[(size_t)n * 8192 + s * 512 + d] = h[s];
}

__device__ __forceinline__ void ln_write(float y, int n, int d,
                                         const float* __restrict__ gamma,
                                         const float* __restrict__ beta,
                                         float* __restrict__ out)
{
    __shared__ float rs[16], rs2[16];
    __syncthreads();
    float v = y, v2 = y * y;
#pragma unroll
    for (int o = 16; o; o >>= 1) {
        v  += __shfl_down_sync(0xffffffffu, v,  o);
        v2 += __shfl_down_sync(0xffffffffu, v2, o);
    }
    int wp = d >> 5, lane = d & 31;
    if (lane == 0) { rs[wp] = v; rs2[wp] = v2; }
    __syncthreads();
    if (wp == 0) {
        float a = (lane < 16) ? rs[lane]  : 0.f;
        float b = (lane < 16) ? rs2[lane] : 0.f;
#pragma unroll
        for (int o = 8; o; o >>= 1) {
            a += __shfl_down_sync(0xffffffffu, a, o);
            b += __shfl_down_sync(0xffffffffu, b, o);
        }
        if (lane == 0) { rs[0] = a * (1.f / 512.f); rs2[0] = b * (1.f / 512.f); }
    }
    __syncthreads();
    float mu = rs[0];
    float var = rs2[0] - mu * mu;
    out[(size_t)n * 512 + d] = (y - mu) * rsqrtf(var + 1e-5f) * gamma[d] + beta[d];
}

__device__ __forceinline__ void readout_ln(int n, int d, const float* __restrict__ h, float xn,
                                           const float* __restrict__ Dv,
                                           const float* __restrict__ gamma,
                                           const float* __restrict__ beta,
                                           float* __restrict__ out)
{
    float y = Dv[d] * xn;
#pragma unroll
    for (int s = 0; s < 16; s++) y = fmaf(h[s], g_Cv[(size_t)n * 16 + s], y);
    ln_write(y, n, d, gamma, beta, out);
}

// ---- levels 0..6: root-path recompute; writes H only for level 6 ----------
__global__ __launch_bounds__(512) void root_kernel(
    const float* __restrict__ Dv, const float* __restrict__ gamma,
    const float* __restrict__ beta, float* __restrict__ out)
{
    int n = blockIdx.x;        // 0..126
    int d = threadIdx.x;
    float h[16];
#pragma unroll
    for (int s = 0; s < 16; s++) h[s] = 0.f;
    float dn = 0.f, xn = 0.f;
    int L = 32 - __clz(n + 1);  // path length
    for (int i = L - 1; i >= 0; i--) {
        int m = ((n + 1) >> i) - 1;
        compute_h(m, d, h, h, dn, xn);
    }
    if (n >= 63) store_h(n, d, h);
    readout_ln(n, d, h, xn, Dv, gamma, beta, out);
}

// ---- two fused levels (l, l+1); writes H only for l+1 ---------------------
__global__ __launch_bounds__(512) void scan2_kernel(
    int base, const float* __restrict__ Dv, const float* __restrict__ gamma,
    const float* __restrict__ beta, float* __restrict__ out)
{
    int n = base + blockIdx.x;
    int d = threadIdx.x;
    int par = (n - 1) >> 1;
    float hp[16];
#pragma unroll
    for (int s = 0; s < 16; s++) hp[s] = g_H[(size_t)par * 8192 + s * 512 + d];
    float h[16], dn, xn;
    compute_h(n, d, hp, h, dn, xn);
    readout_ln(n, d, h, xn, Dv, gamma, beta, out);
#pragma unroll
    for (int ci = 1; ci <= 2; ci++) {
        int c = 2 * n + ci;
        float hc[16], dc, xc;
        compute_h(c, d, h, hc, dc, xc);
        store_h(c, d, hc);
        readout_ln(c, d, hc, xc, Dv, gamma, beta, out);
    }
}

// ---- three fused levels (11, 12, 13); no H writes --------------------------
__global__ __launch_bounds__(512) void scan3_kernel(
    const float* __restrict__ Dv, const float* __restrict__ gamma,
    const float* __restrict__ beta, float* __restrict__ out)
{
    int n = 2047 + blockIdx.x;
    int d = threadIdx.x;
    int par = (n - 1) >> 1;
    float hp[16];
#pragma unroll
    for (int s = 0; s < 16; s++) hp[s] = g_H[(size_t)par * 8192 + s * 512 + d];
    float h1[16], dn, xn;
    compute_h(n, d, hp, h1, dn, xn);
    readout_ln(n, d, h1, xn, Dv, gamma, beta, out);
#pragma unroll
    for (int ci = 1; ci <= 2; ci++) {
        int c = 2 * n + ci;
        float h2[16], dc, xc;
        compute_h(c, d, h1, h2, dc, xc);
        readout_ln(c, d, h2, xc, Dv, gamma, beta, out);
#pragma unroll
        for (int gi = 1; gi <= 2; gi++) {
            int gg = 2 * c + gi;
            float h3[16], dg, xg;
            compute_h(gg, d, h2, h3, dg, xg);
            readout_ln(gg, d, h3, xg, Dv, gamma, beta, out);
        }
    }
}

// ---------------------------------------------------------------------------
extern "C" void kernel_launch(void* const* d_in, const int* in_sizes, int n_in,
                              void* d_out, int out_size)
{
    const float* s    = (const float*)d_in[0];
    const float* w    = (const float*)d_in[1];
    const float* Win  = (const float*)d_in[4];
    const float* bin  = (const float*)d_in[5];
    const float* Wd   = (const float*)d_in[6];
    const float* bd   = (const float*)d_in[7];
    const float* Ww   = (const float*)d_in[8];
    const float* bw   = (const float*)d_in[9];
    const float* Alog = (const float*)d_in[10];
    const float* Dv   = (const float*)d_in[11];
    const float* WB   = (const float*)d_in[12];
    const float* bB   = (const float*)d_in[13];
    const float* WC   = (const float*)d_in[14];
    const float* bC   = (const float*)d_in[15];
    const float* gam  = (const float*)d_in[16];
    const float* bet  = (const float*)d_in[17];
    float* out = (float*)d_out;

    const int SMEM128 = 2 * (8192 + 2 * 128 * 32);   // 32768
    const int SMEM32  = 2 * (8192 + 2 * 32 * 32);    // 20480

    prepW_kernel<<<1024, 256>>>(w, Alog, Win, Wd, WB, WC);
    prepS_kernel<<<8192, 256>>>(s);
    gemm_mma<128, 0><<<dim3(4, 128), 256, SMEM128>>>(bin, Win, nullptr);
    gemm_mma<128, 1><<<dim3(4, 128), 256, SMEM128>>>(bd, Ww, bw);
    gemm_mma<32, 2><<<dim3(1, 128), 256, SMEM32>>>(bB, bC, nullptr);
    root_kernel<<<127, 512>>>(Dv, gam, bet, out);
    scan2_kernel<<<128, 512>>>(127, Dv, gam, bet, out);   // levels 7,8
    scan2_kernel<<<512, 512>>>(511, Dv, gam, bet, out);   // levels 9,10
    scan3_kernel<<<2048, 512>>>(Dv, gam, bet, out);       // levels 11,12,13
}

// round 5
// speedup vs baseline: 1.7592x; 1.1138x over previous
#include <cuda_runtime.h>
#include <cuda_bf16.h>
#include <math.h>
#include <stddef.h>
#include <stdint.h>

#define NNODES 16383
#define NHMAX  2047          // H stored only for nodes < 2047 (levels <= 10)

// ------------------------- device scratch ----------------------------------
__device__ __align__(256) float g_x[(size_t)NNODES * 512];
__device__ __align__(256) float g_delta[(size_t)NNODES * 512];
__device__ __align__(256) float g_Bv[(size_t)NNODES * 16];
__device__ __align__(256) float g_Cv[(size_t)NNODES * 16];
__device__ __align__(256) float g_logw[NNODES];
__device__ __align__(256) float g_negAT[16 * 512];               // [s][d] = -exp(A_log[d][s])
__device__ __align__(256) float g_H[(size_t)NHMAX * 8192];       // [node][s][d]
__device__ __align__(256) __nv_bfloat16 g_S_hl[(size_t)NNODES * 1024];  // [row][hi512|lo512]
__device__ __align__(256) __nv_bfloat16 g_x_hl[(size_t)NNODES * 1024];
__device__ __align__(256) __nv_bfloat16 g_Wi_hl[512 * 1024];
__device__ __align__(256) __nv_bfloat16 g_Wd_hl[512 * 1024];
__device__ __align__(256) __nv_bfloat16 g_BC_hl[32 * 1024];      // rows 0..15 = W_B, 16..31 = W_C

// ------------------------- small helpers -----------------------------------
__device__ __forceinline__ uint32_t smem_u32(const void* p) {
    uint32_t a;
    asm("{ .reg .u64 t; cvta.to.shared.u64 t, %1; cvt.u32.u64 %0, t; }" : "=r"(a) : "l"(p));
    return a;
}
__device__ __forceinline__ void cp16(uint32_t dst, const void* src, int sz) {
    asm volatile("cp.async.cg.shared.global [%0], [%1], 16, %2;"
                 :: "r"(dst), "l"(src), "r"(sz) : "memory");
}
__device__ __forceinline__ void ldsm4(uint32_t* r, uint32_t addr) {
    asm volatile("ldmatrix.sync.aligned.m8n8.x4.shared.b16 {%0,%1,%2,%3}, [%4];"
                 : "=r"(r[0]), "=r"(r[1]), "=r"(r[2]), "=r"(r[3]) : "r"(addr));
}
__device__ __forceinline__ void mma16816(float* c, const uint32_t* a, const uint32_t* b) {
    asm volatile(
        "mma.sync.aligned.m16n8k16.row.col.f32.bf16.bf16.f32 "
        "{%0,%1,%2,%3}, {%4,%5,%6,%7}, {%8,%9}, {%0,%1,%2,%3};"
        : "+f"(c[0]), "+f"(c[1]), "+f"(c[2]), "+f"(c[3])
        : "r"(a[0]), "r"(a[1]), "r"(a[2]), "r"(a[3]), "r"(b[0]), "r"(b[1]));
}
__device__ __forceinline__ void split2(float v, __nv_bfloat16& h, __nv_bfloat16& l) {
    h = __float2bfloat16_rn(v);
    l = __float2bfloat16_rn(v - __bfloat162float(h));
}

// ------------------------- prep kernels ------------------------------------
__global__ void prepW_kernel(const float* __restrict__ w, const float* __restrict__ Alog,
                             const float* __restrict__ Win, const float* __restrict__ Wd,
                             const float* __restrict__ WB, const float* __restrict__ WC)
{
    int i = blockIdx.x * blockDim.x + threadIdx.x;   // 262144 threads
    if (i < 262144) {
        int d = i >> 9, k = i & 511;
        __nv_bfloat16 h, l;
        split2(Win[(size_t)d * 513 + k], h, l);
        g_Wi_hl[(size_t)d * 1024 + k] = h; g_Wi_hl[(size_t)d * 1024 + 512 + k] = l;
        split2(Wd[(size_t)d * 512 + k], h, l);
        g_Wd_hl[(size_t)d * 1024 + k] = h; g_Wd_hl[(size_t)d * 1024 + 512 + k] = l;
    }
    if (i < 16384) {
        int r = i >> 9, k = i & 511;
        float v = (r < 16) ? WB[(size_t)r * 512 + k] : WC[(size_t)(r - 16) * 512 + k];
        __nv_bfloat16 h, l; split2(v, h, l);
        g_BC_hl[(size_t)r * 1024 + k] = h; g_BC_hl[(size_t)r * 1024 + 512 + k] = l;
    }
    if (i < NNODES) g_logw[i] = logf(w[i] + 1e-6f);
    if (i < 8192) {
        int s = i >> 9, d = i & 511;
        g_negAT[i] = -expf(Alog[d * 16 + s]);
    }
}

__global__ void prepS_kernel(const float* __restrict__ s) {
    int idx = blockIdx.x * blockDim.x + threadIdx.x;
    if (idx >= NNODES * 128) return;
    int r = idx >> 7, c4 = idx & 127;
    float4 v = reinterpret_cast<const float4*>(s)[idx];
    __align__(8) __nv_bfloat16 h[4], l[4];
    split2(v.x, h[0], l[0]); split2(v.y, h[1], l[1]);
    split2(v.z, h[2], l[2]); split2(v.w, h[3], l[3]);
    *reinterpret_cast<uint2*>(&g_S_hl[(size_t)r * 1024 + c4 * 4])       = *reinterpret_cast<uint2*>(h);
    *reinterpret_cast<uint2*>(&g_S_hl[(size_t)r * 1024 + 512 + c4 * 4]) = *reinterpret_cast<uint2*>(l);
}

// ------------------------- mma.sync GEMM, BK=32, ldmatrix -------------------
// Stage layout (80B row stride, conflict-free for ldmatrix):
//   A_hi [0,10240)  A_lo [10240,20480)  B_hi [20480,+BTILE)  B_lo [+BTILE]
template <int BN, int EPI>
__global__ __launch_bounds__(256, 1) void gemm_mma(
    const float* __restrict__ p0, const float* __restrict__ p1, const float* __restrict__ p2)
{
    constexpr int MT = (BN == 128) ? 4 : 1;
    constexpr int NT = 4;
    constexpr int BTILE = BN * 80;
    constexpr int STAGE = 20480 + 2 * BTILE;
    constexpr int ACH = 1024;                // A 16B-chunks per stage
    constexpr int NCH = ACH + BN * 8;        // total chunks per stage
    extern __shared__ char smem[];
    uint32_t sb = smem_u32(smem);

    const __nv_bfloat16* __restrict__ Ag = (EPI == 0) ? g_S_hl : g_x_hl;
    const __nv_bfloat16* __restrict__ Bg = (EPI == 0) ? g_Wi_hl : (EPI == 1 ? g_Wd_hl : g_BC_hl);

    const int tid = threadIdx.x;
    const int wid = tid >> 5, lane = tid & 31;
    const int g = lane >> 2, tig = lane & 3;
    const int warp_m = (BN == 128) ? (wid & 1) : wid;
    const int warp_n = (BN == 128) ? (wid >> 1) : 0;
    const int rowBase = blockIdx.y * 128;
    const int colBase = blockIdx.x * BN;
    const int lrow = lane & 15;
    const int lcol = (lane >> 4) * 16;

    float acc[MT][NT][4];
#pragma unroll
    for (int i = 0; i < MT; i++)
#pragma unroll
        for (int j = 0; j < NT; j++)
#pragma unroll
            for (int q = 0; q < 4; q++) acc[i][j][q] = 0.f;

    auto load_stage = [&](int it, int stg) {
        int k0 = it * 32;
        uint32_t D = sb + stg * STAGE;
#pragma unroll
        for (int i = 0; i < NCH / 256; i++) {
            int q = tid + i * 256;
            bool isB = q >= ACH;
            int idx = isB ? q - ACH : q;
            int r = idx >> 3, c = idx & 7;
            int hl = c >> 2, cc = c & 3;
            int grow = isB ? (colBase + r) : (rowBase + r);
            int sz = 16;
            if (!isB && grow >= NNODES) { grow = 0; sz = 0; }
            const __nv_bfloat16* src = (isB ? Bg : Ag) +
                ((size_t)grow * 1024 + hl * 512 + k0 + cc * 8);
            uint32_t dst = D + (isB ? 20480 + hl * BTILE : hl * 10240) + r * 80 + cc * 16;
            cp16(dst, src, sz);
        }
    };

    load_stage(0, 0);
    asm volatile("cp.async.commit_group;" ::: "memory");

    for (int it = 0; it < 16; it++) {
        if (it < 15) load_stage(it + 1, (it + 1) & 1);
        asm volatile("cp.async.commit_group;" ::: "memory");
        asm volatile("cp.async.wait_group 1;" ::: "memory");
        __syncthreads();

        uint32_t SB = sb + (it & 1) * STAGE;
        uint32_t Bb = SB + 20480;
#pragma unroll
        for (int ks = 0; ks < 2; ks++) {
            uint32_t ah[MT][4], al[MT][4], bh[2][4], bl[2][4];
#pragma unroll
            for (int mi = 0; mi < MT; mi++) {
                uint32_t ar = SB + (warp_m * MT * 16 + mi * 16 + lrow) * 80 + ks * 32 + lcol;
                ldsm4(ah[mi], ar);
                ldsm4(al[mi], ar + 10240);
            }
#pragma unroll
            for (int np = 0; np < 2; np++) {
                uint32_t br = Bb + (warp_n * 32 + np * 16 + lrow) * 80 + ks * 32 + lcol;
                ldsm4(bh[np], br);
                ldsm4(bl[np], br + BTILE);
            }
            // product 1: Ah * Bh  (independent across all (mi,ni))
#pragma unroll
            for (int mi = 0; mi < MT; mi++)
#pragma unroll
                for (int ni = 0; ni < NT; ni++) {
                    uint32_t b[2] = { bh[ni >> 1][ni & 1], bh[ni >> 1][2 + (ni & 1)] };
                    mma16816(acc[mi][ni], ah[mi], b);
                }
            // product 2: Ah * Bl
#pragma unroll
            for (int mi = 0; mi < MT; mi++)
#pragma unroll
                for (int ni = 0; ni < NT; ni++) {
                    uint32_t b[2] = { bl[ni >> 1][ni & 1], bl[ni >> 1][2 + (ni & 1)] };
                    mma16816(acc[mi][ni], ah[mi], b);
                }
            // product 3: Al * Bh
#pragma unroll
            for (int mi = 0; mi < MT; mi++)
#pragma unroll
                for (int ni = 0; ni < NT; ni++) {
                    uint32_t b[2] = { bh[ni >> 1][ni & 1], bh[ni >> 1][2 + (ni & 1)] };
                    mma16816(acc[mi][ni], al[mi], b);
                }
        }
        __syncthreads();
    }

    // --------------------------- epilogue -----------------------------------
#pragma unroll
    for (int mi = 0; mi < MT; mi++) {
#pragma unroll
        for (int ni = 0; ni < NT; ni++) {
            int r0 = rowBase + warp_m * MT * 16 + mi * 16 + g;
            int c  = colBase + warp_n * 32 + ni * 8 + tig * 2;
#pragma unroll
            for (int h = 0; h < 2; h++) {
                int r = r0 + h * 8;
                if (r >= NNODES) continue;
                float v0 = acc[mi][ni][h * 2 + 0];
                float v1 = acc[mi][ni][h * 2 + 1];
                if (EPI == 0) {
                    float lw = g_logw[r];
                    float x0 = v0 + p0[c]     + lw * p1[(size_t)c * 513 + 512];
                    float x1 = v1 + p0[c + 1] + lw * p1[(size_t)(c + 1) * 513 + 512];
                    g_x[(size_t)r * 512 + c]     = x0;
                    g_x[(size_t)r * 512 + c + 1] = x1;
                    __nv_bfloat16 h0, l0, h1, l1;
                    split2(x0, h0, l0); split2(x1, h1, l1);
                    __nv_bfloat162 hp; hp.x = h0; hp.y = h1;
                    __nv_bfloat162 lp; lp.x = l0; lp.y = l1;
                    *reinterpret_cast<__nv_bfloat162*>(&g_x_hl[(size_t)r * 1024 + c])       = hp;
                    *reinterpret_cast<__nv_bfloat162*>(&g_x_hl[(size_t)r * 1024 + 512 + c]) = lp;
                } else if (EPI == 1) {
                    float lw = g_logw[r];
                    float z0 = v0 + p0[c], z1 = v1 + p0[c + 1];
                    float sp0 = (z0 > 20.f) ? z0 : log1pf(expf(z0));
                    float sp1 = (z1 > 20.f) ? z1 : log1pf(expf(z1));
                    float t0 = lw * p1[c] + p2[c];
                    float t1 = lw * p1[c + 1] + p2[c + 1];
                    g_delta[(size_t)r * 512 + c]     = sp0 / (1.f + expf(-t0));
                    g_delta[(size_t)r * 512 + c + 1] = sp1 / (1.f + expf(-t1));
                } else {
                    if (c < 16) {
                        g_Bv[(size_t)r * 16 + c]     = v0 + p0[c];
                        g_Bv[(size_t)r * 16 + c + 1] = v1 + p0[c + 1];
                    } else {
                        g_Cv[(size_t)r * 16 + (c - 16)]     = v0 + p1[c - 16];
                        g_Cv[(size_t)r * 16 + (c - 16) + 1] = v1 + p1[c - 15];
                    }
                }
            }
        }
    }
}

// ------------------------- scan building blocks ----------------------------
__device__ __forceinline__ void compute_h(int n, int d, const float* __restrict__ hp,
                                          float* __restrict__ h, float& dn_o, float& xn_o)
{
    float dn = g_delta[(size_t)n * 512 + d];
    float xn = g_x[(size_t)n * 512 + d];
    float dx = dn * xn;
#pragma unroll
    for (int s = 0; s < 16; s++) {
        float a = __expf(dn * g_negAT[s * 512 + d]);
        h[s] = fmaf(a, hp[s], dx * g_Bv[(size_t)n * 16 + s]);
    }
    dn_o = dn; xn_o = xn;
}
__device__ __forceinline__ void store_h(int n, int d, const float* __restrict__ h) {
#pragma unroll
    for (int s = 0; s < 16; s++) g_H[(size_t)n * 8192 + s * 512 + d] = h[s];
}

__device__ __forceinline__ void ln_write(float y, int n, int d,
                                         const float* __restrict__ gamma,
                                         const float* __restrict__ beta,
                                         float* __restrict__ out)
{
    __shared__ float rs[16], rs2[16];
    __syncthreads();
    float v = y, v2 = y * y;
#pragma unroll
    for (int o = 16; o; o >>= 1) {
        v  += __shfl_down_sync(0xffffffffu, v,  o);
        v2 += __shfl_down_sync(0xffffffffu, v2, o);
    }
    int wp = d >> 5, lane = d & 31;
    if (lane == 0) { rs[wp] = v; rs2[wp] = v2; }
    __syncthreads();
    if (wp == 0) {
        float a = (lane < 16) ? rs[lane]  : 0.f;
        float b = (lane < 16) ? rs2[lane] : 0.f;
#pragma unroll
        for (int o = 8; o; o >>= 1) {
            a += __shfl_down_sync(0xffffffffu, a, o);
            b += __shfl_down_sync(0xffffffffu, b, o);
        }
        if (lane == 0) { rs[0] = a * (1.f / 512.f); rs2[0] = b * (1.f / 512.f); }
    }
    __syncthreads();
    float mu = rs[0];
    float var = rs2[0] - mu * mu;
    out[(size_t)n * 512 + d] = (y - mu) * rsqrtf(var + 1e-5f) * gamma[d] + beta[d];
}

__device__ __forceinline__ void readout_ln(int n, int d, const float* __restrict__ h, float xn,
                                           const float* __restrict__ Dv,
                                           const float* __restrict__ gamma,
                                           const float* __restrict__ beta,
                                           float* __restrict__ out)
{
    float y = Dv[d] * xn;
#pragma unroll
    for (int s = 0; s < 16; s++) y = fmaf(h[s], g_Cv[(size_t)n * 16 + s], y);
    ln_write(y, n, d, gamma, beta, out);
}

// ---- levels 0..6: root-path recompute; writes H only for level 6 ----------
__global__ __launch_bounds__(512) void root_kernel(
    const float* __restrict__ Dv, const float* __restrict__ gamma,
    const float* __restrict__ beta, float* __restrict__ out)
{
    int n = blockIdx.x;        // 0..126
    int d = threadIdx.x;
    float h[16];
#pragma unroll
    for (int s = 0; s < 16; s++) h[s] = 0.f;
    float dn = 0.f, xn = 0.f;
    int L = 32 - __clz(n + 1);  // path length
    for (int i = L - 1; i >= 0; i--) {
        int m = ((n + 1) >> i) - 1;
        compute_h(m, d, h, h, dn, xn);
    }
    if (n >= 63) store_h(n, d, h);
    readout_ln(n, d, h, xn, Dv, gamma, beta, out);
}

// ---- two fused levels (l, l+1); writes H only for l+1 ---------------------
__global__ __launch_bounds__(512) void scan2_kernel(
    int base, const float* __restrict__ Dv, const float* __restrict__ gamma,
    const float* __restrict__ beta, float* __restrict__ out)
{
    int n = base + blockIdx.x;
    int d = threadIdx.x;
    int par = (n - 1) >> 1;
    float hp[16];
#pragma unroll
    for (int s = 0; s < 16; s++) hp[s] = g_H[(size_t)par * 8192 + s * 512 + d];
    float h[16], dn, xn;
    compute_h(n, d, hp, h, dn, xn);
    readout_ln(n, d, h, xn, Dv, gamma, beta, out);
#pragma unroll
    for (int ci = 1; ci <= 2; ci++) {
        int c = 2 * n + ci;
        float hc[16], dc, xc;
        compute_h(c, d, h, hc, dc, xc);
        store_h(c, d, hc);
        readout_ln(c, d, hc, xc, Dv, gamma, beta, out);
    }
}

// ---- three fused levels (11, 12, 13); no H writes --------------------------
__global__ __launch_bounds__(512) void scan3_kernel(
    const float* __restrict__ Dv, const float* __restrict__ gamma,
    const float* __restrict__ beta, float* __restrict__ out)
{
    int n = 2047 + blockIdx.x;
    int d = threadIdx.x;
    int par = (n - 1) >> 1;
    float hp[16];
#pragma unroll
    for (int s = 0; s < 16; s++) hp[s] = g_H[(size_t)par * 8192 + s * 512 + d];
    float h1[16], dn, xn;
    compute_h(n, d, hp, h1, dn, xn);
    readout_ln(n, d, h1, xn, Dv, gamma, beta, out);
#pragma unroll
    for (int ci = 1; ci <= 2; ci++) {
        int c = 2 * n + ci;
        float h2[16], dc, xc;
        compute_h(c, d, h1, h2, dc, xc);
        readout_ln(c, d, h2, xc, Dv, gamma, beta, out);
#pragma unroll
        for (int gi = 1; gi <= 2; gi++) {
            int gg = 2 * c + gi;
            float h3[16], dg, xg;
            compute_h(gg, d, h2, h3, dg, xg);
            readout_ln(gg, d, h3, xg, Dv, gamma, beta, out);
        }
    }
}

// ---------------------------------------------------------------------------
extern "C" void kernel_launch(void* const* d_in, const int* in_sizes, int n_in,
                              void* d_out, int out_size)
{
    const float* s    = (const float*)d_in[0];
    const float* w    = (const float*)d_in[1];
    const float* Win  = (const float*)d_in[4];
    const float* bin  = (const float*)d_in[5];
    const float* Wd   = (const float*)d_in[6];
    const float* bd   = (const float*)d_in[7];
    const float* Ww   = (const float*)d_in[8];
    const float* bw   = (const float*)d_in[9];
    const float* Alog = (const float*)d_in[10];
    const float* Dv   = (const float*)d_in[11];
    const float* WB   = (const float*)d_in[12];
    const float* bB   = (const float*)d_in[13];
    const float* WC   = (const float*)d_in[14];
    const float* bC   = (const float*)d_in[15];
    const float* gam  = (const float*)d_in[16];
    const float* bet  = (const float*)d_in[17];
    float* out = (float*)d_out;

    const int SMEM128 = 2 * (20480 + 2 * 128 * 80);   // 81920
    const int SMEM32  = 2 * (20480 + 2 * 32 * 80);    // 51200
    cudaFuncSetAttribute(gemm_mma<128, 0>, cudaFuncAttributeMaxDynamicSharedMemorySize, SMEM128);
    cudaFuncSetAttribute(gemm_mma<128, 1>, cudaFuncAttributeMaxDynamicSharedMemorySize, SMEM128);
    cudaFuncSetAttribute(gemm_mma<32, 2>,  cudaFuncAttributeMaxDynamicSharedMemorySize, SMEM32);

    prepW_kernel<<<1024, 256>>>(w, Alog, Win, Wd, WB, WC);
    prepS_kernel<<<8192, 256>>>(s);
    gemm_mma<128, 0><<<dim3(4, 128), 256, SMEM128>>>(bin, Win, nullptr);
    gemm_mma<128, 1><<<dim3(4, 128), 256, SMEM128>>>(bd, Ww, bw);
    gemm_mma<32, 2><<<dim3(1, 128), 256, SMEM32>>>(bB, bC, nullptr);
    root_kernel<<<127, 512>>>(Dv, gam, bet, out);
    scan2_kernel<<<128, 512>>>(127, Dv, gam, bet, out);   // levels 7,8
    scan2_kernel<<<512, 512>>>(511, Dv, gam, bet, out);   // levels 9,10
    scan3_kernel<<<2048, 512>>>(Dv, gam, bet, out);       // levels 11,12,13
}

// round 6
// speedup vs baseline: 1.9919x; 1.1322x over previous
#include <cuda_runtime.h>
#include <cuda_bf16.h>
#include <math.h>
#include <stddef.h>
#include <stdint.h>

#define NNODES 16383
#define NHMAX  2047          // H stored only for nodes < 2047 (levels <= 10)

// ------------------------- device scratch ----------------------------------
__device__ __align__(256) float g_x[(size_t)NNODES * 512];
__device__ __align__(256) float g_delta[(size_t)NNODES * 512];
__device__ __align__(256) float g_Bv[(size_t)NNODES * 16];
__device__ __align__(256) float g_Cv[(size_t)NNODES * 16];
__device__ __align__(256) float g_logw[NNODES];
__device__ __align__(256) float g_negAT[16 * 512];               // [s][d] = -exp(A_log[d][s])
__device__ __align__(256) float g_H[(size_t)NHMAX * 8192];       // [node][s][d]
__device__ __align__(256) __nv_bfloat16 g_S_hl[(size_t)NNODES * 1024];  // [row][hi512|lo512]
__device__ __align__(256) __nv_bfloat16 g_x_hl[(size_t)NNODES * 1024];
__device__ __align__(256) __nv_bfloat16 g_Wi_hl[512 * 1024];
__device__ __align__(256) __nv_bfloat16 g_Wd_hl[512 * 1024];
__device__ __align__(256) __nv_bfloat16 g_BC_hl[32 * 1024];      // rows 0..15 = W_B, 16..31 = W_C

// ------------------------- small helpers -----------------------------------
__device__ __forceinline__ uint32_t smem_u32(const void* p) {
    uint32_t a;
    asm("{ .reg .u64 t; cvta.to.shared.u64 t, %1; cvt.u32.u64 %0, t; }" : "=r"(a) : "l"(p));
    return a;
}
__device__ __forceinline__ void cp16(uint32_t dst, const void* src, int sz) {
    asm volatile("cp.async.cg.shared.global [%0], [%1], 16, %2;"
                 :: "r"(dst), "l"(src), "r"(sz) : "memory");
}
__device__ __forceinline__ void ldsm4(uint32_t* r, uint32_t addr) {
    asm volatile("ldmatrix.sync.aligned.m8n8.x4.shared.b16 {%0,%1,%2,%3}, [%4];"
                 : "=r"(r[0]), "=r"(r[1]), "=r"(r[2]), "=r"(r[3]) : "r"(addr));
}
__device__ __forceinline__ void mma16816(float* c, const uint32_t* a, const uint32_t* b) {
    asm volatile(
        "mma.sync.aligned.m16n8k16.row.col.f32.bf16.bf16.f32 "
        "{%0,%1,%2,%3}, {%4,%5,%6,%7}, {%8,%9}, {%0,%1,%2,%3};"
        : "+f"(c[0]), "+f"(c[1]), "+f"(c[2]), "+f"(c[3])
        : "r"(a[0]), "r"(a[1]), "r"(a[2]), "r"(a[3]), "r"(b[0]), "r"(b[1]));
}
__device__ __forceinline__ void split2(float v, __nv_bfloat16& h, __nv_bfloat16& l) {
    h = __float2bfloat16_rn(v);
    l = __float2bfloat16_rn(v - __bfloat162float(h));
}

// ------------------------- prep kernels ------------------------------------
__global__ void prepW_kernel(const float* __restrict__ w, const float* __restrict__ Alog,
                             const float* __restrict__ Win, const float* __restrict__ Wd,
                             const float* __restrict__ WB, const float* __restrict__ WC)
{
    int i = blockIdx.x * blockDim.x + threadIdx.x;   // 262144 threads
    if (i < 262144) {
        int d = i >> 9, k = i & 511;
        __nv_bfloat16 h, l;
        split2(Win[(size_t)d * 513 + k], h, l);
        g_Wi_hl[(size_t)d * 1024 + k] = h; g_Wi_hl[(size_t)d * 1024 + 512 + k] = l;
        split2(Wd[(size_t)d * 512 + k], h, l);
        g_Wd_hl[(size_t)d * 1024 + k] = h; g_Wd_hl[(size_t)d * 1024 + 512 + k] = l;
    }
    if (i < 16384) {
        int r = i >> 9, k = i & 511;
        float v = (r < 16) ? WB[(size_t)r * 512 + k] : WC[(size_t)(r - 16) * 512 + k];
        __nv_bfloat16 h, l; split2(v, h, l);
        g_BC_hl[(size_t)r * 1024 + k] = h; g_BC_hl[(size_t)r * 1024 + 512 + k] = l;
    }
    if (i < NNODES) g_logw[i] = logf(w[i] + 1e-6f);
    if (i < 8192) {
        int s = i >> 9, d = i & 511;
        g_negAT[i] = -expf(Alog[d * 16 + s]);
    }
}

__global__ void prepS_kernel(const float* __restrict__ s) {
    int idx = blockIdx.x * blockDim.x + threadIdx.x;
    if (idx >= NNODES * 128) return;
    int r = idx >> 7, c4 = idx & 127;
    float4 v = reinterpret_cast<const float4*>(s)[idx];
    __align__(8) __nv_bfloat16 h[4], l[4];
    split2(v.x, h[0], l[0]); split2(v.y, h[1], l[1]);
    split2(v.z, h[2], l[2]); split2(v.w, h[3], l[3]);
    *reinterpret_cast<uint2*>(&g_S_hl[(size_t)r * 1024 + c4 * 4])       = *reinterpret_cast<uint2*>(h);
    *reinterpret_cast<uint2*>(&g_S_hl[(size_t)r * 1024 + 512 + c4 * 4]) = *reinterpret_cast<uint2*>(l);
}

// ------------------------- mma.sync GEMM, BK=32, ldmatrix -------------------
// Stage layout (80B row stride, conflict-free for ldmatrix):
//   A_hi [0,10240)  A_lo [10240,20480)  B_hi [20480,+BTILE)  B_lo [+BTILE]
template <int BN, int EPI>
__global__ __launch_bounds__(256, 2) void gemm_mma(
    const float* __restrict__ p0, const float* __restrict__ p1, const float* __restrict__ p2)
{
    constexpr int MT = (BN == 128) ? 4 : 1;
    constexpr int NT = 4;
    constexpr int BTILE = BN * 80;
    constexpr int STAGE = 20480 + 2 * BTILE;
    constexpr int ACH = 1024;                // A 16B-chunks per stage
    constexpr int NCH = ACH + BN * 8;        // total chunks per stage
    constexpr int CPT = NCH / 256;           // chunks per thread
    extern __shared__ char smem[];
    uint32_t sb = smem_u32(smem);

    const __nv_bfloat16* __restrict__ Ag = (EPI == 0) ? g_S_hl : g_x_hl;
    const __nv_bfloat16* __restrict__ Bg = (EPI == 0) ? g_Wi_hl : (EPI == 1 ? g_Wd_hl : g_BC_hl);
    const char* Agc = (const char*)Ag;
    const char* Bgc = (const char*)Bg;

    const int tid = threadIdx.x;
    const int wid = tid >> 5, lane = tid & 31;
    const int g = lane >> 2, tig = lane & 3;
    const int warp_m = (BN == 128) ? (wid & 1) : wid;
    const int warp_n = (BN == 128) ? (wid >> 1) : 0;
    const int rowBase = blockIdx.y * 128;
    const int colBase = blockIdx.x * BN;
    const int lrow = lane & 15;
    const int lcol = (lane >> 4) * 16;

    // ---- hoisted cp.async addressing (per-thread, computed once) ----------
    uint32_t off[CPT], dstc[CPT];
    int szv[CPT];
#pragma unroll
    for (int i = 0; i < CPT; i++) {
        int q = tid + i * 256;
        if (i * 256 < ACH) {               // A chunk (compile-time branch)
            int r = q >> 3, c = q & 7;
            int hl = c >> 2, cc = c & 3;
            int grow = rowBase + r;
            int sz = 16;
            if (grow >= NNODES) { grow = 0; sz = 0; }
            off[i]  = ((uint32_t)grow * 1024u + (uint32_t)(hl * 512 + cc * 8)) * 2u;
            dstc[i] = hl * 10240 + r * 80 + cc * 16;
            szv[i]  = sz;
        } else {                            // B chunk
            int idx = q - ACH;
            int r = idx >> 3, c = idx & 7;
            int hl = c >> 2, cc = c & 3;
            off[i]  = ((uint32_t)(colBase + r) * 1024u + (uint32_t)(hl * 512 + cc * 8)) * 2u;
            dstc[i] = 20480 + hl * BTILE + r * 80 + cc * 16;
            szv[i]  = 16;
        }
    }

    float acc[MT][NT][4];
#pragma unroll
    for (int i = 0; i < MT; i++)
#pragma unroll
        for (int j = 0; j < NT; j++)
#pragma unroll
            for (int q = 0; q < 4; q++) acc[i][j][q] = 0.f;

    auto load_stage = [&](int it, int stg) {
        uint32_t D = sb + stg * STAGE;
        uint32_t kadd = (uint32_t)it * 64u;
#pragma unroll
        for (int i = 0; i < CPT; i++) {
            const char* src = ((i * 256 >= ACH) ? Bgc : Agc) + off[i] + kadd;
            cp16(D + dstc[i], src, szv[i]);
        }
    };

    load_stage(0, 0);
    asm volatile("cp.async.commit_group;" ::: "memory");

    for (int it = 0; it < 16; it++) {
        if (it < 15) load_stage(it + 1, (it + 1) & 1);
        asm volatile("cp.async.commit_group;" ::: "memory");
        asm volatile("cp.async.wait_group 1;" ::: "memory");
        __syncthreads();

        uint32_t SB = sb + (it & 1) * STAGE;
        uint32_t Bb = SB + 20480;
#pragma unroll
        for (int ks = 0; ks < 2; ks++) {
            uint32_t ah[MT][4], al[MT][4], bh[2][4], bl[2][4];
#pragma unroll
            for (int mi = 0; mi < MT; mi++) {
                uint32_t ar = SB + (warp_m * MT * 16 + mi * 16 + lrow) * 80 + ks * 32 + lcol;
                ldsm4(ah[mi], ar);
                ldsm4(al[mi], ar + 10240);
            }
#pragma unroll
            for (int np = 0; np < 2; np++) {
                uint32_t br = Bb + (warp_n * 32 + np * 16 + lrow) * 80 + ks * 32 + lcol;
                ldsm4(bh[np], br);
                ldsm4(bl[np], br + BTILE);
            }
            // product 1: Ah * Bh  (independent across all (mi,ni))
#pragma unroll
            for (int mi = 0; mi < MT; mi++)
#pragma unroll
                for (int ni = 0; ni < NT; ni++) {
                    uint32_t b[2] = { bh[ni >> 1][ni & 1], bh[ni >> 1][2 + (ni & 1)] };
                    mma16816(acc[mi][ni], ah[mi], b);
                }
            // product 2: Ah * Bl
#pragma unroll
            for (int mi = 0; mi < MT; mi++)
#pragma unroll
                for (int ni = 0; ni < NT; ni++) {
                    uint32_t b[2] = { bl[ni >> 1][ni & 1], bl[ni >> 1][2 + (ni & 1)] };
                    mma16816(acc[mi][ni], ah[mi], b);
                }
            // product 3: Al * Bh
#pragma unroll
            for (int mi = 0; mi < MT; mi++)
#pragma unroll
                for (int ni = 0; ni < NT; ni++) {
                    uint32_t b[2] = { bh[ni >> 1][ni & 1], bh[ni >> 1][2 + (ni & 1)] };
                    mma16816(acc[mi][ni], al[mi], b);
                }
        }
        __syncthreads();
    }

    // --------------------------- epilogue -----------------------------------
#pragma unroll
    for (int mi = 0; mi < MT; mi++) {
#pragma unroll
        for (int ni = 0; ni < NT; ni++) {
            int r0 = rowBase + warp_m * MT * 16 + mi * 16 + g;
            int c  = colBase + warp_n * 32 + ni * 8 + tig * 2;
#pragma unroll
            for (int h = 0; h < 2; h++) {
                int r = r0 + h * 8;
                if (r >= NNODES) continue;
                float v0 = acc[mi][ni][h * 2 + 0];
                float v1 = acc[mi][ni][h * 2 + 1];
                if (EPI == 0) {
                    float lw = g_logw[r];
                    float x0 = v0 + p0[c]     + lw * p1[(size_t)c * 513 + 512];
                    float x1 = v1 + p0[c + 1] + lw * p1[(size_t)(c + 1) * 513 + 512];
                    g_x[(size_t)r * 512 + c]     = x0;
                    g_x[(size_t)r * 512 + c + 1] = x1;
                    __nv_bfloat16 h0, l0, h1, l1;
                    split2(x0, h0, l0); split2(x1, h1, l1);
                    __nv_bfloat162 hp; hp.x = h0; hp.y = h1;
                    __nv_bfloat162 lp; lp.x = l0; lp.y = l1;
                    *reinterpret_cast<__nv_bfloat162*>(&g_x_hl[(size_t)r * 1024 + c])       = hp;
                    *reinterpret_cast<__nv_bfloat162*>(&g_x_hl[(size_t)r * 1024 + 512 + c]) = lp;
                } else if (EPI == 1) {
                    float lw = g_logw[r];
                    float z0 = v0 + p0[c], z1 = v1 + p0[c + 1];
                    float sp0 = (z0 > 20.f) ? z0 : log1pf(expf(z0));
                    float sp1 = (z1 > 20.f) ? z1 : log1pf(expf(z1));
                    float t0 = lw * p1[c] + p2[c];
                    float t1 = lw * p1[c + 1] + p2[c + 1];
                    g_delta[(size_t)r * 512 + c]     = sp0 / (1.f + expf(-t0));
                    g_delta[(size_t)r * 512 + c + 1] = sp1 / (1.f + expf(-t1));
                } else {
                    if (c < 16) {
                        g_Bv[(size_t)r * 16 + c]     = v0 + p0[c];
                        g_Bv[(size_t)r * 16 + c + 1] = v1 + p0[c + 1];
                    } else {
                        g_Cv[(size_t)r * 16 + (c - 16)]     = v0 + p1[c - 16];
                        g_Cv[(size_t)r * 16 + (c - 16) + 1] = v1 + p1[c - 15];
                    }
                }
            }
        }
    }
}

// ------------------------- scan building blocks ----------------------------
__device__ __forceinline__ void compute_h(int n, int d, const float* __restrict__ hp,
                                          float* __restrict__ h, float& dn_o, float& xn_o)
{
    float dn = g_delta[(size_t)n * 512 + d];
    float xn = g_x[(size_t)n * 512 + d];
    float dx = dn * xn;
#pragma unroll
    for (int s = 0; s < 16; s++) {
        float a = __expf(dn * g_negAT[s * 512 + d]);
        h[s] = fmaf(a, hp[s], dx * g_Bv[(size_t)n * 16 + s]);
    }
    dn_o = dn; xn_o = xn;
}
__device__ __forceinline__ void store_h(int n, int d, const float* __restrict__ h) {
#pragma unroll
    for (int s = 0; s < 16; s++) g_H[(size_t)n * 8192 + s * 512 + d] = h[s];
}

__device__ __forceinline__ void ln_write(float y, int n, int d,
                                         const float* __restrict__ gamma,
                                         const float* __restrict__ beta,
                                         float* __restrict__ out)
{
    __shared__ float rs[16], rs2[16];
    __syncthreads();
    float v = y, v2 = y * y;
#pragma unroll
    for (int o = 16; o; o >>= 1) {
        v  += __shfl_down_sync(0xffffffffu, v,  o);
        v2 += __shfl_down_sync(0xffffffffu, v2, o);
    }
    int wp = d >> 5, lane = d & 31;
    if (lane == 0) { rs[wp] = v; rs2[wp] = v2; }
    __syncthreads();
    if (wp == 0) {
        float a = (lane < 16) ? rs[lane]  : 0.f;
        float b = (lane < 16) ? rs2[lane] : 0.f;
#pragma unroll
        for (int o = 8; o; o >>= 1) {
            a += __shfl_down_sync(0xffffffffu, a, o);
            b += __shfl_down_sync(0xffffffffu, b, o);
        }
        if (lane == 0) { rs[0] = a * (1.f / 512.f); rs2[0] = b * (1.f / 512.f); }
    }
    __syncthreads();
    float mu = rs[0];
    float var = rs2[0] - mu * mu;
    out[(size_t)n * 512 + d] = (y - mu) * rsqrtf(var + 1e-5f) * gamma[d] + beta[d];
}

__device__ __forceinline__ void readout_ln(int n, int d, const float* __restrict__ h, float xn,
                                           const float* __restrict__ Dv,
                                           const float* __restrict__ gamma,
                                           const float* __restrict__ beta,
                                           float* __restrict__ out)
{
    float y = Dv[d] * xn;
#pragma unroll
    for (int s = 0; s < 16; s++) y = fmaf(h[s], g_Cv[(size_t)n * 16 + s], y);
    ln_write(y, n, d, gamma, beta, out);
}

// ---- levels 0..6: root-path recompute; writes H only for level 6 ----------
__global__ __launch_bounds__(512) void root_kernel(
    const float* __restrict__ Dv, const float* __restrict__ gamma,
    const float* __restrict__ beta, float* __restrict__ out)
{
    int n = blockIdx.x;        // 0..126
    int d = threadIdx.x;
    float h[16];
#pragma unroll
    for (int s = 0; s < 16; s++) h[s] = 0.f;
    float dn = 0.f, xn = 0.f;
    int L = 32 - __clz(n + 1);  // path length
    for (int i = L - 1; i >= 0; i--) {
        int m = ((n + 1) >> i) - 1;
        compute_h(m, d, h, h, dn, xn);
    }
    if (n >= 63) store_h(n, d, h);
    readout_ln(n, d, h, xn, Dv, gamma, beta, out);
}

// ---- two fused levels (l, l+1); writes H only for l+1 ---------------------
__global__ __launch_bounds__(512) void scan2_kernel(
    int base, const float* __restrict__ Dv, const float* __restrict__ gamma,
    const float* __restrict__ beta, float* __restrict__ out)
{
    int n = base + blockIdx.x;
    int d = threadIdx.x;
    int par = (n - 1) >> 1;
    float hp[16];
#pragma unroll
    for (int s = 0; s < 16; s++) hp[s] = g_H[(size_t)par * 8192 + s * 512 + d];
    float h[16], dn, xn;
    compute_h(n, d, hp, h, dn, xn);
    readout_ln(n, d, h, xn, Dv, gamma, beta, out);
#pragma unroll
    for (int ci = 1; ci <= 2; ci++) {
        int c = 2 * n + ci;
        float hc[16], dc, xc;
        compute_h(c, d, h, hc, dc, xc);
        store_h(c, d, hc);
        readout_ln(c, d, hc, xc, Dv, gamma, beta, out);
    }
}

// ---- three fused levels (11, 12, 13); no H writes --------------------------
__global__ __launch_bounds__(512) void scan3_kernel(
    const float* __restrict__ Dv, const float* __restrict__ gamma,
    const float* __restrict__ beta, float* __restrict__ out)
{
    int n = 2047 + blockIdx.x;
    int d = threadIdx.x;
    int par = (n - 1) >> 1;
    float hp[16];
#pragma unroll
    for (int s = 0; s < 16; s++) hp[s] = g_H[(size_t)par * 8192 + s * 512 + d];
    float h1[16], dn, xn;
    compute_h(n, d, hp, h1, dn, xn);
    readout_ln(n, d, h1, xn, Dv, gamma, beta, out);
#pragma unroll
    for (int ci = 1; ci <= 2; ci++) {
        int c = 2 * n + ci;
        float h2[16], dc, xc;
        compute_h(c, d, h1, h2, dc, xc);
        readout_ln(c, d, h2, xc, Dv, gamma, beta, out);
#pragma unroll
        for (int gi = 1; gi <= 2; gi++) {
            int gg = 2 * c + gi;
            float h3[16], dg, xg;
            compute_h(gg, d, h2, h3, dg, xg);
            readout_ln(gg, d, h3, xg, Dv, gamma, beta, out);
        }
    }
}

// ---------------------------------------------------------------------------
extern "C" void kernel_launch(void* const* d_in, const int* in_sizes, int n_in,
                              void* d_out, int out_size)
{
    const float* s    = (const float*)d_in[0];
    const float* w    = (const float*)d_in[1];
    const float* Win  = (const float*)d_in[4];
    const float* bin  = (const float*)d_in[5];
    const float* Wd   = (const float*)d_in[6];
    const float* bd   = (const float*)d_in[7];
    const float* Ww   = (const float*)d_in[8];
    const float* bw   = (const float*)d_in[9];
    const float* Alog = (const float*)d_in[10];
    const float* Dv   = (const float*)d_in[11];
    const float* WB   = (const float*)d_in[12];
    const float* bB   = (const float*)d_in[13];
    const float* WC   = (const float*)d_in[14];
    const float* bC   = (const float*)d_in[15];
    const float* gam  = (const float*)d_in[16];
    const float* bet  = (const float*)d_in[17];
    float* out = (float*)d_out;

    const int SMEM128 = 2 * (20480 + 2 * 128 * 80);   // 81920
    const int SMEM32  = 2 * (20480 + 2 * 32 * 80);    // 51200
    cudaFuncSetAttribute(gemm_mma<128, 0>, cudaFuncAttributeMaxDynamicSharedMemorySize, SMEM128);
    cudaFuncSetAttribute(gemm_mma<128, 1>, cudaFuncAttributeMaxDynamicSharedMemorySize, SMEM128);
    cudaFuncSetAttribute(gemm_mma<32, 2>,  cudaFuncAttributeMaxDynamicSharedMemorySize, SMEM32);

    prepW_kernel<<<1024, 256>>>(w, Alog, Win, Wd, WB, WC);
    prepS_kernel<<<8192, 256>>>(s);
    gemm_mma<128, 0><<<dim3(4, 128), 256, SMEM128>>>(bin, Win, nullptr);
    gemm_mma<128, 1><<<dim3(4, 128), 256, SMEM128>>>(bd, Ww, bw);
    gemm_mma<32, 2><<<dim3(1, 128), 256, SMEM32>>>(bB, bC, nullptr);
    root_kernel<<<127, 512>>>(Dv, gam, bet, out);
    scan2_kernel<<<128, 512>>>(127, Dv, gam, bet, out);   // levels 7,8
    scan2_kernel<<<512, 512>>>(511, Dv, gam, bet, out);   // levels 9,10
    scan3_kernel<<<2048, 512>>>(Dv, gam, bet, out);       // levels 11,12,13
}